// round 13
// baseline (speedup 1.0000x reference)
#include <cuda_runtime.h>
#include <cuda_fp16.h>
#include <cstdint>

#define BATCH 8
#define SEQ   2048
#define CDIM  1024
#define HDIM  64
#define BT    (BATCH*SEQ)

// fp16 planes (packed u32 pairs), written by proj, read by attn (all hi-only)
__device__ uint32_t g_q[BT*32];     // q pre-scaled by log2(e)/32
__device__ uint32_t g_k[BT*32];
__device__ uint32_t g_v[BT*32];

// ---------------- helpers ----------------
__device__ __forceinline__ uint32_t smem_u32(const void* p){
    uint32_t a; asm("{ .reg .u64 t; cvta.to.shared.u64 t, %1; cvt.u32.u64 %0, t; }" : "=r"(a) : "l"(p)); return a;
}
__device__ __forceinline__ void ldm4(uint32_t* r, uint32_t a){
    asm volatile("ldmatrix.sync.aligned.m8n8.x4.shared.b16 {%0,%1,%2,%3},[%4];"
        : "=r"(r[0]),"=r"(r[1]),"=r"(r[2]),"=r"(r[3]) : "r"(a));
}
__device__ __forceinline__ void ldm4t(uint32_t* r, uint32_t a){
    asm volatile("ldmatrix.sync.aligned.m8n8.x4.trans.shared.b16 {%0,%1,%2,%3},[%4];"
        : "=r"(r[0]),"=r"(r[1]),"=r"(r[2]),"=r"(r[3]) : "r"(a));
}
__device__ __forceinline__ void mma16816(float* d, const uint32_t* a, const uint32_t* b){
    asm volatile("mma.sync.aligned.m16n8k16.row.col.f32.f16.f16.f32 "
        "{%0,%1,%2,%3},{%4,%5,%6,%7},{%8,%9},{%0,%1,%2,%3};"
        : "+f"(d[0]),"+f"(d[1]),"+f"(d[2]),"+f"(d[3])
        : "r"(a[0]),"r"(a[1]),"r"(a[2]),"r"(a[3]),"r"(b[0]),"r"(b[1]));
}
__device__ __forceinline__ uint32_t pk2(float x, float y){
    __half2 t = __floats2half2_rn(x, y); return *(uint32_t*)&t;
}
__device__ __forceinline__ uint32_t aA(uint32_t base, int lane, int SB){
    return base + (uint32_t)((lane&15)*SB + (lane>>4)*16);
}
__device__ __forceinline__ uint32_t aB(uint32_t base, int lane, int SB){
    return base + (uint32_t)(((((lane>>4)&1)<<3) + (lane&7))*SB + ((lane>>3)&1)*16);
}
#define CPA16(dst, src) asm volatile("cp.async.cg.shared.global [%0], [%1], 16;" :: "r"(dst), "l"(src))
#define CP_COMMIT()     asm volatile("cp.async.commit_group;")
#define CP_WAIT0()      asm volatile("cp.async.wait_group 0;" ::: "memory")

// ---------------- kernel 1: fused QKV projection (single-term, double-buffered) --------
#define PX  0
#define PB  18432            // 64 rows x 400B (192 f16 + pad)
#define PBUF 44032
#define PJ_SMEM 88064
__global__ __launch_bounds__(512,1) void proj_mma(
    const float* __restrict__ x, const float* __restrict__ Wk,
    const float* __restrict__ Wq, const float* __restrict__ Wv)
{
    extern __shared__ char sm[];
    const uint32_t sb = smem_u32(sm);
    const int tid=threadIdx.x, lane=tid&31, wid=tid>>5;
    const int wm=wid>>2, wn=wid&3, g=lane>>2, tig=lane&3;
    const int m0 = blockIdx.x*128;
    const float* Ws[3] = {Wk, Wq, Wv};

    float4 xr[4], wr[6];
    #pragma unroll
    for (int i=0;i<4;++i){ int lin=tid+i*512, row=lin>>4, c4=(lin&15)*4;
        xr[i] = *(const float4*)(x + (size_t)(m0+row)*CDIM + c4); }
    #pragma unroll
    for (int i=0;i<6;++i){ int lin=tid+i*512, row=lin/48, c4=(lin-row*48)*4;
        wr[i] = *(const float4*)(Ws[c4>>6] + (size_t)row*HDIM + (c4&63)); }
    #pragma unroll
    for (int i=0;i<4;++i){ int lin=tid+i*512, row=lin>>4, c4=(lin&15)*4;
        *(uint2*)(sm + PX + row*144 + c4*2) = make_uint2(pk2(xr[i].x,xr[i].y), pk2(xr[i].z,xr[i].w)); }
    #pragma unroll
    for (int i=0;i<6;++i){ int lin=tid+i*512, row=lin/48, c4=(lin-row*48)*4;
        *(uint2*)(sm + PB + row*400 + c4*2) = make_uint2(pk2(wr[i].x,wr[i].y), pk2(wr[i].z,wr[i].w)); }
    __syncthreads();

    float acc[2][3][2][4] = {};
    for (int c=0;c<16;++c){
        uint32_t pbu = sb + (c&1)*PBUF;
        if (c<15){
            #pragma unroll
            for (int i=0;i<4;++i){ int lin=tid+i*512, row=lin>>4, c4=(lin&15)*4;
                xr[i] = *(const float4*)(x + (size_t)(m0+row)*CDIM + (c+1)*64 + c4); }
            #pragma unroll
            for (int i=0;i<6;++i){ int lin=tid+i*512, row=lin/48, c4=(lin-row*48)*4;
                wr[i] = *(const float4*)(Ws[c4>>6] + (size_t)((c+1)*64+row)*HDIM + (c4&63)); }
        }
        #pragma unroll
        for (int ks=0;ks<4;++ks){
            int k0 = ks*16;
            uint32_t ah[2][4];
            #pragma unroll
            for (int mi=0;mi<2;++mi)
                ldm4(ah[mi], aA(pbu + PX + (wm*32+mi*16)*144 + k0*2, lane, 144));
            #pragma unroll
            for (int nt=0;nt<3;++nt){
                uint32_t bh[4];
                ldm4t(bh, aA(pbu + PB + k0*400 + (wn+nt*4)*32, lane, 400));
                #pragma unroll
                for (int mi=0;mi<2;++mi)
                    #pragma unroll
                    for (int n8=0;n8<2;++n8)
                        mma16816(acc[mi][nt][n8], ah[mi], bh+n8*2);
            }
        }
        if (c<15){
            char* nb = sm + ((c+1)&1)*PBUF;
            #pragma unroll
            for (int i=0;i<4;++i){ int lin=tid+i*512, row=lin>>4, c4=(lin&15)*4;
                *(uint2*)(nb + PX + row*144 + c4*2) = make_uint2(pk2(xr[i].x,xr[i].y), pk2(xr[i].z,xr[i].w)); }
            #pragma unroll
            for (int i=0;i<6;++i){ int lin=tid+i*512, row=lin/48, c4=(lin-row*48)*4;
                *(uint2*)(nb + PB + row*400 + c4*2) = make_uint2(pk2(wr[i].x,wr[i].y), pk2(wr[i].z,wr[i].w)); }
        }
        __syncthreads();
    }
    #pragma unroll
    for (int mi=0;mi<2;++mi)
        #pragma unroll
        for (int nt=0;nt<3;++nt)
            #pragma unroll
            for (int n8=0;n8<2;++n8){
                int ncol = (wn+nt*4)*16 + n8*8 + tig*2;
                int cc = ncol&63;
                int r0 = m0 + wm*32 + mi*16 + g;
                float* a = acc[mi][nt][n8];
                uint32_t* dst = (nt==0)? g_k : (nt==1)? g_q : g_v;
                float s = (nt==1)? 0.03125f*1.44269504f : 1.f;   // fold log2(e) for exp2
                dst[((size_t)r0*64+cc)>>1]     = pk2(a[0]*s, a[1]*s);
                dst[((size_t)(r0+8)*64+cc)>>1] = pk2(a[2]*s, a[3]*s);
            }
}

// ---------------- kernel 2: attention (256 thr, 4m x 2n warps of 32x64, cp.async) ------
// Warp = 32 q-rows x 64 keys. Register P. 1 sync/iter. 2-way O reduce at end.
#define AQ    0
#define AKV0  18432          // per buffer: K +0 | V +18432 (36864 B); two buffers
#define AKVSZ 36864
#define AOP   92160          // partial O: 128 x 64 f32 = 32768
#define ALP   124928         // partial lsum: 128 f32
#define AT_SMEM 125440
__global__ __launch_bounds__(256,1) void attn_mma(float* __restrict__ out){
    extern __shared__ char sm[];
    const uint32_t sb = smem_u32(sm);
    const int tid=threadIdx.x, lane=tid&31, wid=tid>>5;
    const int wm=wid>>1, wn=wid&1, g=lane>>2, tig=lane&3;
    const int b=blockIdx.y, q0=blockIdx.x*128;

    // stage Q (plain stores) + KV tile 0 via cp.async
    #pragma unroll
    for (int i=0;i<4;++i){
        int lin=tid+i*256, row=lin>>3, c8h=(lin&7)*4;
        *(uint4*)(sm + AQ + row*144 + c8h*4) =
            *(const uint4*)(g_q + ((size_t)(b*SEQ+q0)+row)*32 + c8h);
    }
    #pragma unroll
    for (int i=0;i<8;++i){
        int lin=tid+i*256, plane=lin>>10, rem=lin&1023, row=rem>>3, c8h=(rem&7)*4;
        const uint32_t* gp = plane? g_v : g_k;
        CPA16(sb + AKV0 + plane*18432 + row*144 + c8h*4,
              gp + ((size_t)(b*SEQ)+row)*32 + c8h);
    }
    CP_COMMIT(); CP_WAIT0();
    __syncthreads();

    // hoist Q fragments (warp rows wm*32..+32, invariant over t)
    uint32_t qf[4][2][4];
    #pragma unroll
    for (int ks=0;ks<4;++ks)
        #pragma unroll
        for (int mi=0;mi<2;++mi)
            ldm4(qf[ks][mi], aA(sb + AQ + (wm*32+mi*16)*144 + ks*32, lane, 144));

    float oacc[2][8][4] = {};
    float lsum[4] = {};
    for (int t=0;t<16;++t){
        uint32_t kvb = sb + AKV0 + (t&1)*AKVSZ;
        if (t<15){
            uint32_t nbuf = sb + AKV0 + ((t+1)&1)*AKVSZ;
            #pragma unroll
            for (int i=0;i<8;++i){
                int lin=tid+i*256, plane=lin>>10, rem=lin&1023, row=rem>>3, c8h=(rem&7)*4;
                const uint32_t* gp = plane? g_v : g_k;
                CPA16(nbuf + plane*18432 + row*144 + c8h*4,
                      gp + ((size_t)(b*SEQ)+(t+1)*128+row)*32 + c8h);
            }
            CP_COMMIT();
        }
        // ---- S = Q K^T (warp: 32 rows x 64 keys) ----
        float sacc[2][8][4] = {};
        #pragma unroll
        for (int ks=0;ks<4;++ks){
            #pragma unroll
            for (int nt=0;nt<4;++nt){
                uint32_t kf[4];
                ldm4(kf, aB(kvb + (wn*64+nt*16)*144 + ks*32, lane, 144));
                #pragma unroll
                for (int mi=0;mi<2;++mi){
                    mma16816(sacc[mi][nt*2+0], qf[ks][mi], kf+0);
                    mma16816(sacc[mi][nt*2+1], qf[ks][mi], kf+2);
                }
            }
        }
        // ---- exp2 + pack P into A-fragments (registers only) ----
        uint32_t pa[2][4][4];
        #pragma unroll
        for (int mi=0;mi<2;++mi)
            #pragma unroll
            for (int j=0;j<4;++j){
                float e0=exp2f(sacc[mi][2*j][0]),   e1=exp2f(sacc[mi][2*j][1]);
                float e2=exp2f(sacc[mi][2*j][2]),   e3=exp2f(sacc[mi][2*j][3]);
                float e4=exp2f(sacc[mi][2*j+1][0]), e5=exp2f(sacc[mi][2*j+1][1]);
                float e6=exp2f(sacc[mi][2*j+1][2]), e7=exp2f(sacc[mi][2*j+1][3]);
                lsum[mi*2+0] += (e0+e1)+(e4+e5);
                lsum[mi*2+1] += (e2+e3)+(e6+e7);
                pa[mi][j][0]=pk2(e0,e1); pa[mi][j][1]=pk2(e2,e3);
                pa[mi][j][2]=pk2(e4,e5); pa[mi][j][3]=pk2(e6,e7);
            }
        // ---- O_partial += P V ----
        #pragma unroll
        for (int ks=0;ks<4;++ks){
            #pragma unroll
            for (int nc=0;nc<4;++nc){
                uint32_t vh[4];
                ldm4t(vh, aA(kvb + 18432 + (wn*64+ks*16)*144 + nc*32, lane, 144));
                #pragma unroll
                for (int mi=0;mi<2;++mi){
                    mma16816(oacc[mi][nc*2+0], pa[mi][ks], vh+0);
                    mma16816(oacc[mi][nc*2+1], pa[mi][ks], vh+2);
                }
            }
        }
        if (t<15) CP_WAIT0();
        __syncthreads();
    }
    // ---- reduce lsum over tig lanes ----
    #pragma unroll
    for (int i=0;i<4;++i){
        lsum[i] += __shfl_xor_sync(0xffffffffu, lsum[i], 1);
        lsum[i] += __shfl_xor_sync(0xffffffffu, lsum[i], 2);
    }
    // ---- cross-warp (wn pair) O + lsum reduction ----
    float* op = (float*)(sm + AOP) + wm*32*64;
    float* lp = (float*)(sm + ALP);
    if (wn==1){
        #pragma unroll
        for (int mi=0;mi<2;++mi)
            #pragma unroll
            for (int n8=0;n8<8;++n8){
                int col = n8*8 + tig*2;
                *(float2*)(op + (mi*16+g)*64 + col)   = make_float2(oacc[mi][n8][0], oacc[mi][n8][1]);
                *(float2*)(op + (mi*16+g+8)*64 + col) = make_float2(oacc[mi][n8][2], oacc[mi][n8][3]);
            }
        if (tig==0){
            #pragma unroll
            for (int i=0;i<4;++i)
                lp[wm*32 + (i>>1)*16 + (i&1)*8 + g] = lsum[i];
        }
    }
    __syncthreads();
    if (wn==0){
        float inv[4];
        #pragma unroll
        for (int i=0;i<4;++i)
            inv[i] = 1.f/(lsum[i] + lp[wm*32 + (i>>1)*16 + (i&1)*8 + g]);
        float* og = out + ((size_t)b*SEQ + q0 + wm*32)*HDIM;
        #pragma unroll
        for (int mi=0;mi<2;++mi)
            #pragma unroll
            for (int n8=0;n8<8;++n8){
                int col = n8*8 + tig*2;
                float2 p0 = *(float2*)(op + (mi*16+g)*64 + col);
                float2 p1 = *(float2*)(op + (mi*16+g+8)*64 + col);
                *(float2*)(og + (size_t)(mi*16+g)*HDIM + col) =
                    make_float2((oacc[mi][n8][0]+p0.x)*inv[mi*2], (oacc[mi][n8][1]+p0.y)*inv[mi*2]);
                *(float2*)(og + (size_t)(mi*16+g+8)*HDIM + col) =
                    make_float2((oacc[mi][n8][2]+p1.x)*inv[mi*2+1], (oacc[mi][n8][3]+p1.y)*inv[mi*2+1]);
            }
    }
}

extern "C" void kernel_launch(void* const* d_in, const int* in_sizes, int n_in,
                              void* d_out, int out_size)
{
    const float* x  = (const float*)d_in[0];
    const float* Wk = (const float*)d_in[1];
    const float* Wq = (const float*)d_in[2];
    const float* Wv = (const float*)d_in[3];
    float* out = (float*)d_out;

    cudaFuncSetAttribute(proj_mma, cudaFuncAttributeMaxDynamicSharedMemorySize, PJ_SMEM);
    cudaFuncSetAttribute(attn_mma, cudaFuncAttributeMaxDynamicSharedMemorySize, AT_SMEM);

    proj_mma<<<BT/128, 512, PJ_SMEM>>>(x, Wk, Wq, Wv);
    attn_mma<<<dim3(SEQ/128, BATCH), 256, AT_SMEM>>>(out);
}